// round 9
// baseline (speedup 1.0000x reference)
#include <cuda_runtime.h>

// Problem constants
#define GAMMA 0.1f
#define TAU   0.01f
#define NN    256          // neuron count
#define MM    512          // astrocyte count
#define KK    512          // input dim
#define NN2   (NN * NN)    // 65536
#define SPLIT 8            // chunks per H row (32 KB each)
#define CHUNK (NN2 / SPLIT) // 8192 floats per chunk

#define SETUP_BLKS 32
#define D_ROWS_PER_BLK 16
#define D_BLKS   (NN2 / D_ROWS_PER_BLK)   // 4096
#define H_BLKS   (MM * SPLIT)             // 4096
#define D_START  SETUP_BLKS               // 32
#define H_START  (SETUP_BLKS + D_BLKS)    // 4128
#define TOTAL_BLKS (SETUP_BLKS + D_BLKS + H_BLKS)  // 8224
#define CONSUMERS (D_BLKS + H_BLKS)       // 8192

// Scratch (no allocations allowed in kernel_launch). Zero-init at load;
// all counters/flags self-reset each run for graph replay.
__device__ float g_phi[NN];           // sigmoid(x_new)
__device__ float g_part[MM * SPLIT];  // H@Phi partial sums (chunk 0 folds win2)
__device__ int   g_cnt[MM];           // per-row H-chunk arrival counters
__device__ int   g_done;              // setup-block completion counter
__device__ int   g_fin;               // consumer-block completion counter
__device__ volatile int g_flag;       // phi-ready flag

__device__ __forceinline__ float warp_sum(float v) {
#pragma unroll
    for (int o = 16; o > 0; o >>= 1) v += __shfl_xor_sync(0xffffffffu, v, o);
    return v;
}

__device__ __forceinline__ float sigmoidf(float v) {
    return 1.0f / (1.0f + expf(-v));
}

// ---------------------------------------------------------------------------
// Mega-kernel: 8224 blocks x 256 threads.
//   [0, 32)        setup: x_new + phi (warp-per-row), release g_flag
//   [32, 4128)     W_new: D GEMV 2 rows/warp; ONE block-level gate before the
//                  phi-dependent epilogue (tid<16 writes 16 rows)
//   [4128, 8224)   H@Phi 32KB-chunk partials (chunk 0 folds Win2@I);
//                  last chunk per row combines z_new. Gate at block start
//                  (these run waves later — flag long set).
// Last consumer block resets g_flag/g_fin for the next graph replay.
// ---------------------------------------------------------------------------
__global__ void __launch_bounds__(256) kBig(
    const float* __restrict__ x,    const float* __restrict__ W,
    const float* __restrict__ Win1, const float* __restrict__ I,
    const float* __restrict__ Win2, const float* __restrict__ C,
    const float* __restrict__ D,    const float* __restrict__ z,
    const float* __restrict__ H,    const float* __restrict__ F,
    float* __restrict__ out_x, float* __restrict__ out_W,
    float* __restrict__ out_z) {

    __shared__ float s_vec[MM];
    __shared__ float s_red[8];
    __shared__ float s_acc[D_ROWS_PER_BLK];
    int tid  = threadIdx.x;  // 256
    int warp = tid >> 5, lane = tid & 31;
    unsigned bid = blockIdx.x;

    if (bid < SETUP_BLKS) {
        // ================= setup: x_new + phi (8 rows/block) =================
        s_vec[tid]       = sigmoidf(x[tid]);     // s_vec[0..255] = sigmoid(x)
        s_vec[tid + 256] = I[tid + 256];         // s_vec[256..511] = I hi half
        __shared__ float s_Ilo[256];
        s_Ilo[tid] = I[tid];
        __syncthreads();

        int row = bid * 8 + warp;
        float a1 = 0.0f, a2 = 0.0f;
        const float* wr = W + (size_t)row * NN;
#pragma unroll
        for (int j = lane; j < NN; j += 32) a1 += wr[j] * s_vec[j];
        const float* w1 = Win1 + (size_t)row * KK;
#pragma unroll
        for (int k = lane; k < 256; k += 32) {
            a2 += w1[k] * s_Ilo[k] + w1[k + 256] * s_vec[k + 256];
        }
        a1 = warp_sum(a1);
        a2 = warp_sum(a2);
        if (lane == 0) {
            float xn = (1.0f - GAMMA) * x[row] + GAMMA * a1 + a2;
            out_x[row] = xn;
            g_phi[row] = sigmoidf(xn);
            __threadfence();                 // publish phi (8 per block)
        }
        __syncthreads();
        if (tid == 0) {
            int old = atomicAdd(&g_done, 1);
            if (old == SETUP_BLKS - 1) { g_done = 0; g_flag = 1; }  // release
        }
    } else if (bid < H_START) {
        // ========== W_new: 2 rows/warp D GEMV; gated phi epilogue ==========
        s_vec[tid]       = tanhf(z[tid]);
        s_vec[tid + 256] = tanhf(z[tid + 256]);
        __syncthreads();

        int pb = (bid - D_START) * D_ROWS_PER_BLK;   // block's base row
        int p0 = pb + warp * 2;                      // rows p0, p0+1
        const float4* dr0 = (const float4*)(D + (size_t)p0 * MM);
        const float4* dr1 = (const float4*)(D + (size_t)(p0 + 1) * MM);
        const float4* ps  = (const float4*)s_vec;

        float4 a0[4], a1[4];
#pragma unroll
        for (int q = 0; q < 4; q++) a0[q] = dr0[lane + 32 * q];  // 8 loads
#pragma unroll
        for (int q = 0; q < 4; q++) a1[q] = dr1[lane + 32 * q];  // in flight

        float acc0 = 0.0f, acc1 = 0.0f;
#pragma unroll
        for (int q = 0; q < 4; q++) {
            float4 s = ps[lane + 32 * q];
            acc0 += a0[q].x * s.x + a0[q].y * s.y + a0[q].z * s.z + a0[q].w * s.w;
            acc1 += a1[q].x * s.x + a1[q].y * s.y + a1[q].z * s.z + a1[q].w * s.w;
        }
        acc0 = warp_sum(acc0);
        acc1 = warp_sum(acc1);
        if (lane == 0) {
            s_acc[warp * 2]     = acc0;
            s_acc[warp * 2 + 1] = acc1;
        }
        if (tid == 0) {                      // ONE gate per block
            if (g_flag == 0) { while (g_flag == 0) __nanosleep(256); }
            __threadfence();                 // acquire
        }
        __syncthreads();
        if (tid < D_ROWS_PER_BLK) {
            int p = pb + tid;
            float ph = g_phi[p >> 8] * g_phi[p & 255];
            out_W[p] = (1.0f - GAMMA) * W[p] + GAMMA * (C[p] * ph + s_acc[tid]);
        }
        if (tid == 0) {
            int o = atomicAdd(&g_fin, 1);
            if (o == CONSUMERS - 1) { g_fin = 0; g_flag = 0; }  // replay reset
        }
    } else {
        // ========== H@Phi 32KB-chunk partials (+win2 on chunk 0) ==========
        if (tid == 0) {                      // gate (flag long set by now)
            if (g_flag == 0) { while (g_flag == 0) __nanosleep(256); }
            __threadfence();                 // acquire
        }
        __syncthreads();
        s_vec[tid] = g_phi[tid];
        __syncthreads();

        int b = bid - H_START;
        int c = b & (SPLIT - 1);  // chunk
        int m = b >> 3;           // row
        const float4* hr = (const float4*)(H + (size_t)m * NN2 + (size_t)c * CHUNK);

        float4 h[8];
#pragma unroll
        for (int q = 0; q < 8; q++) h[q] = hr[tid + 256 * q];  // 8 in flight

        float acc = 0.0f;
#pragma unroll
        for (int q = 0; q < 8; q++) {
            int p = c * CHUNK + (tid + 256 * q) * 4;  // element index in row
            int i = p >> 8;
            int j = p & 255;              // multiple of 4, j+3 <= 255
            float pi = s_vec[i];
            acc += pi * (h[q].x * s_vec[j]     + h[q].y * s_vec[j + 1] +
                         h[q].z * s_vec[j + 2] + h[q].w * s_vec[j + 3]);
        }
        if (c == 0) {
            // fold (W_in_2 @ I)[m] into this chunk's partial
            const float* w2 = Win2 + (size_t)m * KK;
            acc += w2[tid] * I[tid] + w2[tid + 256] * I[tid + 256];
        }
        acc = warp_sum(acc);
        if (lane == 0) s_red[warp] = acc;
        __syncthreads();
        if (tid == 0) {
            float t = 0.0f;
#pragma unroll
            for (int w = 0; w < 8; w++) t += s_red[w];
            g_part[m * SPLIT + c] = t;
            __threadfence();                       // publish partial
            int old = atomicAdd(&g_cnt[m], 1);
            if (old == SPLIT - 1) {
                // last chunk of row m: combine (deterministic fixed order)
                g_cnt[m] = 0;                      // reset for next replay
                __threadfence();                   // acquire others' partials
                float s = 0.0f;
#pragma unroll
                for (int c2 = 0; c2 < SPLIT; c2++) s += g_part[m * SPLIT + c2];
                float zm  = z[m];
                float psi = tanhf(zm);
                out_z[m] = (1.0f - GAMMA * TAU) * zm +
                           (GAMMA * TAU) * (F[m] * psi + s);
            }
            int o = atomicAdd(&g_fin, 1);
            if (o == CONSUMERS - 1) { g_fin = 0; g_flag = 0; }  // replay reset
        }
    }
}

// ---------------------------------------------------------------------------
// Launch: inputs in metadata order: I, x, W, z, C, D, F, H, W_in_1, W_in_2.
// Output: concat(x_new[256], W_new[65536], z_new[512]) = 66304 floats.
// ---------------------------------------------------------------------------
extern "C" void kernel_launch(void* const* d_in, const int* in_sizes, int n_in,
                              void* d_out, int out_size) {
    const float* I    = (const float*)d_in[0];
    const float* x    = (const float*)d_in[1];
    const float* W    = (const float*)d_in[2];
    const float* z    = (const float*)d_in[3];
    const float* C    = (const float*)d_in[4];
    const float* D    = (const float*)d_in[5];
    const float* F    = (const float*)d_in[6];
    const float* H    = (const float*)d_in[7];
    const float* Win1 = (const float*)d_in[8];
    const float* Win2 = (const float*)d_in[9];

    float* out_x = (float*)d_out;            // [0, 256)
    float* out_W = out_x + NN;               // [256, 256+65536)
    float* out_z = out_W + NN2;              // [65792, 66304)

    kBig<<<TOTAL_BLKS, 256>>>(x, W, Win1, I, Win2, C, D, z, H, F,
                              out_x, out_W, out_z);
}

// round 10
// speedup vs baseline: 1.1263x; 1.1263x over previous
#include <cuda_runtime.h>

// Problem constants
#define GAMMA 0.1f
#define TAU   0.01f
#define NN    256          // neuron count
#define MM    512          // astrocyte count
#define KK    512          // input dim
#define NN2   (NN * NN)    // 65536
#define SPLIT 8            // chunks per H row (32 KB each)
#define CHUNK (NN2 / SPLIT) // 8192 floats per chunk

#define SETUP_BLKS 32
#define D_ROWS_PER_BLK 16
#define D_BLKS   (NN2 / D_ROWS_PER_BLK)   // 4096
#define KD_BLKS  (SETUP_BLKS + D_BLKS)    // 4128

#define H_BLKS   (MM * SPLIT)             // 4096
#define FIX_BLKS (NN2 / (256 * 4))        // 64 fixup blocks (float4/thread)
#define KH_BLKS  (H_BLKS + FIX_BLKS)      // 4160

// Scratch (no allocations allowed in kernel_launch)
__device__ float g_phi[NN];           // sigmoid(x_new)
__device__ float g_part[MM * SPLIT];  // H@Phi partial sums (chunk 0 folds win2)
__device__ int   g_cnt[MM];           // per-row H-chunk arrival counters (self-reset)

__device__ __forceinline__ float warp_sum(float v) {
#pragma unroll
    for (int o = 16; o > 0; o >>= 1) v += __shfl_xor_sync(0xffffffffu, v, o);
    return v;
}

__device__ __forceinline__ float sigmoidf(float v) {
    return 1.0f / (1.0f + expf(-v));
}

// ---------------------------------------------------------------------------
// Kernel 1 (kD): 4128 blocks x 256 threads. NO internal dependencies.
//   blocks [0, 32)    : x_new + g_phi (warp-per-row; hides under D stream)
//   blocks [32, 4128) : W_new PARTIAL = (1-g)W + g*(D@psi(z))  — phi-free!
// ---------------------------------------------------------------------------
__global__ void __launch_bounds__(256) kD(
    const float* __restrict__ x,    const float* __restrict__ W,
    const float* __restrict__ Win1, const float* __restrict__ I,
    const float* __restrict__ D,    const float* __restrict__ z,
    float* __restrict__ out_x, float* __restrict__ out_W) {

    __shared__ float s_vec[MM];
    int tid  = threadIdx.x;  // 256
    int warp = tid >> 5, lane = tid & 31;
    unsigned bid = blockIdx.x;

    if (bid < SETUP_BLKS) {
        // ================= setup: x_new + phi (8 rows/block) =================
        __shared__ float s_Ilo[256];
        s_vec[tid]       = sigmoidf(x[tid]);     // s_vec[0..255] = sigmoid(x)
        s_vec[tid + 256] = I[tid + 256];         // s_vec[256..511] = I hi half
        s_Ilo[tid] = I[tid];
        __syncthreads();

        int row = bid * 8 + warp;
        float a1 = 0.0f, a2 = 0.0f;
        const float* wr = W + (size_t)row * NN;
#pragma unroll
        for (int j = lane; j < NN; j += 32) a1 += wr[j] * s_vec[j];
        const float* w1 = Win1 + (size_t)row * KK;
#pragma unroll
        for (int k = lane; k < 256; k += 32) {
            a2 += w1[k] * s_Ilo[k] + w1[k + 256] * s_vec[k + 256];
        }
        a1 = warp_sum(a1);
        a2 = warp_sum(a2);
        if (lane == 0) {
            float xn = (1.0f - GAMMA) * x[row] + GAMMA * a1 + a2;
            out_x[row] = xn;
            g_phi[row] = sigmoidf(xn);
        }
    } else {
        // ========== W_new partial: 2 rows/warp D GEMV (no phi) ==========
        s_vec[tid]       = tanhf(z[tid]);
        s_vec[tid + 256] = tanhf(z[tid + 256]);
        __syncthreads();

        int p0 = (bid - SETUP_BLKS) * D_ROWS_PER_BLK + warp * 2;  // rows p0, p0+1
        const float4* dr0 = (const float4*)(D + (size_t)p0 * MM);
        const float4* dr1 = (const float4*)(D + (size_t)(p0 + 1) * MM);
        const float4* ps  = (const float4*)s_vec;

        float4 a0[4], a1[4];
#pragma unroll
        for (int q = 0; q < 4; q++) a0[q] = dr0[lane + 32 * q];  // 8 loads
#pragma unroll
        for (int q = 0; q < 4; q++) a1[q] = dr1[lane + 32 * q];  // in flight

        float acc0 = 0.0f, acc1 = 0.0f;
#pragma unroll
        for (int q = 0; q < 4; q++) {
            float4 s = ps[lane + 32 * q];
            acc0 += a0[q].x * s.x + a0[q].y * s.y + a0[q].z * s.z + a0[q].w * s.w;
            acc1 += a1[q].x * s.x + a1[q].y * s.y + a1[q].z * s.z + a1[q].w * s.w;
        }
        acc0 = warp_sum(acc0);
        acc1 = warp_sum(acc1);
        if (lane == 0) {
            out_W[p0]     = (1.0f - GAMMA) * W[p0]     + GAMMA * acc0;
            out_W[p0 + 1] = (1.0f - GAMMA) * W[p0 + 1] + GAMMA * acc1;
        }
    }
}

// ---------------------------------------------------------------------------
// Kernel 2 (kH): 4160 blocks x 256 threads. phi ready via kernel boundary.
//   blocks [0, 4096)    : H@Phi 32KB-chunk partials (chunk 0 folds Win2@I);
//                         last chunk per row combines z_new.
//   blocks [4096, 4160) : Hebbian fixup: out_W[p] += g*C[p]*phi_i*phi_j
// ---------------------------------------------------------------------------
__global__ void __launch_bounds__(256) kH(
    const float* __restrict__ H, const float* __restrict__ F,
    const float* __restrict__ Win2, const float* __restrict__ I,
    const float* __restrict__ C, const float* __restrict__ z,
    float* __restrict__ out_W, float* __restrict__ out_z) {

    __shared__ float s_vec[NN];
    __shared__ float s_red[8];
    int tid  = threadIdx.x;  // 256
    int warp = tid >> 5, lane = tid & 31;
    unsigned bid = blockIdx.x;

    s_vec[tid] = g_phi[tid];
    __syncthreads();

    if (bid < H_BLKS) {
        // ========== H@Phi partials, 32 KB/block (+win2 on chunk 0) ==========
        int c = bid & (SPLIT - 1);  // chunk
        int m = bid >> 3;           // row
        const float4* hr = (const float4*)(H + (size_t)m * NN2 + (size_t)c * CHUNK);

        float4 h[8];
#pragma unroll
        for (int q = 0; q < 8; q++) h[q] = hr[tid + 256 * q];  // 8 in flight

        float acc = 0.0f;
#pragma unroll
        for (int q = 0; q < 8; q++) {
            int p = c * CHUNK + (tid + 256 * q) * 4;  // element index in row
            int i = p >> 8;
            int j = p & 255;              // multiple of 4, j+3 <= 255
            float pi = s_vec[i];
            acc += pi * (h[q].x * s_vec[j]     + h[q].y * s_vec[j + 1] +
                         h[q].z * s_vec[j + 2] + h[q].w * s_vec[j + 3]);
        }
        if (c == 0) {
            // fold (W_in_2 @ I)[m] into this chunk's partial
            const float* w2 = Win2 + (size_t)m * KK;
            acc += w2[tid] * I[tid] + w2[tid + 256] * I[tid + 256];
        }
        acc = warp_sum(acc);
        if (lane == 0) s_red[warp] = acc;
        __syncthreads();
        if (tid == 0) {
            float t = 0.0f;
#pragma unroll
            for (int w = 0; w < 8; w++) t += s_red[w];
            g_part[m * SPLIT + c] = t;
            __threadfence();                       // publish partial
            int old = atomicAdd(&g_cnt[m], 1);
            if (old == SPLIT - 1) {
                // last chunk of row m: combine (deterministic fixed order)
                g_cnt[m] = 0;                      // reset for next replay
                __threadfence();                   // acquire others' partials
                float s = 0.0f;
#pragma unroll
                for (int c2 = 0; c2 < SPLIT; c2++) s += g_part[m * SPLIT + c2];
                float zm  = z[m];
                float psi = tanhf(zm);
                out_z[m] = (1.0f - GAMMA * TAU) * zm +
                           (GAMMA * TAU) * (F[m] * psi + s);
            }
        }
    } else {
        // ========== Hebbian fixup: out_W += g*C*phi_i*phi_j (float4) ==========
        int idx = (bid - H_BLKS) * 256 + tid;   // float4 index, 0..16383
        int p = idx * 4;
        int i = p >> 8;
        int j = p & 255;                        // j..j+3 in same row i
        float pi = s_vec[i];
        float4 cc = ((const float4*)C)[idx];
        float4 w  = ((float4*)out_W)[idx];
        w.x += GAMMA * cc.x * pi * s_vec[j];
        w.y += GAMMA * cc.y * pi * s_vec[j + 1];
        w.z += GAMMA * cc.z * pi * s_vec[j + 2];
        w.w += GAMMA * cc.w * pi * s_vec[j + 3];
        ((float4*)out_W)[idx] = w;
    }
}

// ---------------------------------------------------------------------------
// Launch: inputs in metadata order: I, x, W, z, C, D, F, H, W_in_1, W_in_2.
// Output: concat(x_new[256], W_new[65536], z_new[512]) = 66304 floats.
// ---------------------------------------------------------------------------
extern "C" void kernel_launch(void* const* d_in, const int* in_sizes, int n_in,
                              void* d_out, int out_size) {
    const float* I    = (const float*)d_in[0];
    const float* x    = (const float*)d_in[1];
    const float* W    = (const float*)d_in[2];
    const float* z    = (const float*)d_in[3];
    const float* C    = (const float*)d_in[4];
    const float* D    = (const float*)d_in[5];
    const float* F    = (const float*)d_in[6];
    const float* H    = (const float*)d_in[7];
    const float* Win1 = (const float*)d_in[8];
    const float* Win2 = (const float*)d_in[9];

    float* out_x = (float*)d_out;            // [0, 256)
    float* out_W = out_x + NN;               // [256, 256+65536)
    float* out_z = out_W + NN2;              // [65792, 66304)

    // Kernel 1: x_new/phi setup runs concurrently with the phi-free D stream
    kD<<<KD_BLKS, 256>>>(x, W, Win1, I, D, z, out_x, out_W);

    // Kernel 2: H stream (phi via kernel boundary) + Hebbian fixup + z tail
    kH<<<KH_BLKS, 256>>>(H, F, Win2, I, C, z, out_W, out_z);
}

// round 11
// speedup vs baseline: 1.1572x; 1.0274x over previous
#include <cuda_runtime.h>

// Problem constants
#define GAMMA 0.1f
#define TAU   0.01f
#define NN    256          // neuron count
#define MM    512          // astrocyte count
#define KK    512          // input dim
#define NN2   (NN * NN)    // 65536
#define SPLIT 8            // chunks per H row (32 KB each)
#define CHUNK (NN2 / SPLIT) // 8192 floats per chunk

#define SETUP_BLKS 32
#define D_ROWS_PER_BLK 16

// Kernel 1: setup + first slice of D (phi-free partial)
#define PRE_D_BLKS  1024
#define PRE_D_ROWS  (PRE_D_BLKS * D_ROWS_PER_BLK)   // 16384
#define KPRE_BLKS   (SETUP_BLKS + PRE_D_BLKS)       // 1056

// Kernel 2: remaining D (with Hebbian) striped 3:4 with H, + fixup tail
#define MAIN_D_BLKS 3072                             // rows 16384..65535
#define H_BLKS      (MM * SPLIT)                     // 4096
#define STRIPE_BLKS (MAIN_D_BLKS + H_BLKS)           // 7168 = 1024 * 7
#define FIX_BLKS    (PRE_D_ROWS / (256 * 4))         // 16
#define KMAIN_BLKS  (STRIPE_BLKS + FIX_BLKS)         // 7184

// Scratch (no allocations allowed in kernel_launch)
__device__ float g_phi[NN];           // sigmoid(x_new)
__device__ float g_part[MM * SPLIT];  // H@Phi partial sums (chunk 0 folds win2)
__device__ int   g_cnt[MM];           // per-row H-chunk arrival counters (self-reset)

__device__ __forceinline__ float warp_sum(float v) {
#pragma unroll
    for (int o = 16; o > 0; o >>= 1) v += __shfl_xor_sync(0xffffffffu, v, o);
    return v;
}

__device__ __forceinline__ float sigmoidf(float v) {
    return 1.0f / (1.0f + expf(-v));
}

// ---------------------------------------------------------------------------
// Kernel 1 (kPre): 1056 blocks x 256 threads. NO internal dependencies.
//   blocks [0, 32)     : x_new + g_phi (warp-per-row; hides under D stream)
//   blocks [32, 1056)  : W_new PARTIAL = (1-g)W + g*(D@psi) for rows [0,16384)
// ---------------------------------------------------------------------------
__global__ void __launch_bounds__(256) kPre(
    const float* __restrict__ x,    const float* __restrict__ W,
    const float* __restrict__ Win1, const float* __restrict__ I,
    const float* __restrict__ D,    const float* __restrict__ z,
    float* __restrict__ out_x, float* __restrict__ out_W) {

    __shared__ float s_vec[MM];
    int tid  = threadIdx.x;  // 256
    int warp = tid >> 5, lane = tid & 31;
    unsigned bid = blockIdx.x;

    if (bid < SETUP_BLKS) {
        // ================= setup: x_new + phi (8 rows/block) =================
        __shared__ float s_Ilo[256];
        s_vec[tid]       = sigmoidf(x[tid]);     // s_vec[0..255] = sigmoid(x)
        s_vec[tid + 256] = I[tid + 256];         // s_vec[256..511] = I hi half
        s_Ilo[tid] = I[tid];
        __syncthreads();

        int row = bid * 8 + warp;
        float a1 = 0.0f, a2 = 0.0f;
        const float* wr = W + (size_t)row * NN;
#pragma unroll
        for (int j = lane; j < NN; j += 32) a1 += wr[j] * s_vec[j];
        const float* w1 = Win1 + (size_t)row * KK;
#pragma unroll
        for (int k = lane; k < 256; k += 32) {
            a2 += w1[k] * s_Ilo[k] + w1[k + 256] * s_vec[k + 256];
        }
        a1 = warp_sum(a1);
        a2 = warp_sum(a2);
        if (lane == 0) {
            float xn = (1.0f - GAMMA) * x[row] + GAMMA * a1 + a2;
            out_x[row] = xn;
            g_phi[row] = sigmoidf(xn);
        }
    } else {
        // ========== W_new partial: 2 rows/warp D GEMV (no phi) ==========
        s_vec[tid]       = tanhf(z[tid]);
        s_vec[tid + 256] = tanhf(z[tid + 256]);
        __syncthreads();

        int p0 = (bid - SETUP_BLKS) * D_ROWS_PER_BLK + warp * 2;  // rows p0, p0+1
        const float4* dr0 = (const float4*)(D + (size_t)p0 * MM);
        const float4* dr1 = (const float4*)(D + (size_t)(p0 + 1) * MM);
        const float4* ps  = (const float4*)s_vec;

        float4 a0[4], a1[4];
#pragma unroll
        for (int q = 0; q < 4; q++) a0[q] = dr0[lane + 32 * q];  // 8 loads
#pragma unroll
        for (int q = 0; q < 4; q++) a1[q] = dr1[lane + 32 * q];  // in flight

        float acc0 = 0.0f, acc1 = 0.0f;
#pragma unroll
        for (int q = 0; q < 4; q++) {
            float4 s = ps[lane + 32 * q];
            acc0 += a0[q].x * s.x + a0[q].y * s.y + a0[q].z * s.z + a0[q].w * s.w;
            acc1 += a1[q].x * s.x + a1[q].y * s.y + a1[q].z * s.z + a1[q].w * s.w;
        }
        acc0 = warp_sum(acc0);
        acc1 = warp_sum(acc1);
        if (lane == 0) {
            out_W[p0]     = (1.0f - GAMMA) * W[p0]     + GAMMA * acc0;
            out_W[p0 + 1] = (1.0f - GAMMA) * W[p0 + 1] + GAMMA * acc1;
        }
    }
}

// ---------------------------------------------------------------------------
// Kernel 2 (kMain): 7184 blocks x 256 threads. phi ready via kernel boundary.
//   blocks [0, 7168) striped by bid%7:
//     r<3 : D block (rows >= 16384) with Hebbian term applied directly
//     r>=3: H@Phi 32KB-chunk partial (chunk 0 folds Win2@I); last chunk per
//           row combines z_new
//   blocks [7168, 7184): Hebbian fixup for kPre's rows [0, 16384)
// Striping keeps every wave a D/H mix (pure-load D fills HBM gaps left by
// the compute-heavier H stream).
// ---------------------------------------------------------------------------
__global__ void __launch_bounds__(256) kMain(
    const float* __restrict__ W, const float* __restrict__ C,
    const float* __restrict__ D, const float* __restrict__ z,
    const float* __restrict__ H, const float* __restrict__ F,
    const float* __restrict__ Win2, const float* __restrict__ I,
    float* __restrict__ out_W, float* __restrict__ out_z) {

    __shared__ float s_vec[MM];   // psi(z) for D branch; phi for H branch
    __shared__ float s_phi[NN];   // phi (D branch Hebbian + fixup)
    __shared__ float s_red[8];
    int tid  = threadIdx.x;  // 256
    int warp = tid >> 5, lane = tid & 31;
    unsigned bid = blockIdx.x;

    if (bid < STRIPE_BLKS) {
        int grp = bid / 7;
        int r   = bid - grp * 7;
        if (r < 3) {
            // ========== D: 2 rows/warp GEMV + Hebbian (phi ready) ==========
            int dIdx = grp * 3 + r;                        // 0..3071
            s_vec[tid]       = tanhf(z[tid]);
            s_vec[tid + 256] = tanhf(z[tid + 256]);
            s_phi[tid]       = g_phi[tid];
            __syncthreads();

            int p0 = PRE_D_ROWS + dIdx * D_ROWS_PER_BLK + warp * 2;
            const float4* dr0 = (const float4*)(D + (size_t)p0 * MM);
            const float4* dr1 = (const float4*)(D + (size_t)(p0 + 1) * MM);
            const float4* ps  = (const float4*)s_vec;

            float4 a0[4], a1[4];
#pragma unroll
            for (int q = 0; q < 4; q++) a0[q] = dr0[lane + 32 * q];
#pragma unroll
            for (int q = 0; q < 4; q++) a1[q] = dr1[lane + 32 * q];

            float acc0 = 0.0f, acc1 = 0.0f;
#pragma unroll
            for (int q = 0; q < 4; q++) {
                float4 s = ps[lane + 32 * q];
                acc0 += a0[q].x * s.x + a0[q].y * s.y + a0[q].z * s.z + a0[q].w * s.w;
                acc1 += a1[q].x * s.x + a1[q].y * s.y + a1[q].z * s.z + a1[q].w * s.w;
            }
            acc0 = warp_sum(acc0);
            acc1 = warp_sum(acc1);
            if (lane == 0) {
                int i = p0 >> 8;                 // p0 even => same i both rows
                int j0 = p0 & 255;
                float pi = s_phi[i];
                float ph0 = pi * s_phi[j0];
                float ph1 = pi * s_phi[j0 + 1];
                out_W[p0]     = (1.0f - GAMMA) * W[p0]
                              + GAMMA * (C[p0] * ph0 + acc0);
                out_W[p0 + 1] = (1.0f - GAMMA) * W[p0 + 1]
                              + GAMMA * (C[p0 + 1] * ph1 + acc1);
            }
        } else {
            // ========== H@Phi partial, 32 KB/block (+win2 on chunk 0) ========
            int hIdx = grp * 4 + (r - 3);                  // 0..4095
            s_vec[tid] = g_phi[tid];
            __syncthreads();

            int c = hIdx & (SPLIT - 1);  // chunk
            int m = hIdx >> 3;           // row
            const float4* hr = (const float4*)(H + (size_t)m * NN2 + (size_t)c * CHUNK);

            float4 h[8];
#pragma unroll
            for (int q = 0; q < 8; q++) h[q] = hr[tid + 256 * q];  // 8 in flight

            float acc = 0.0f;
#pragma unroll
            for (int q = 0; q < 8; q++) {
                int p = c * CHUNK + (tid + 256 * q) * 4;  // element index in row
                int i = p >> 8;
                int j = p & 255;              // multiple of 4, j+3 <= 255
                float pi = s_vec[i];
                acc += pi * (h[q].x * s_vec[j]     + h[q].y * s_vec[j + 1] +
                             h[q].z * s_vec[j + 2] + h[q].w * s_vec[j + 3]);
            }
            if (c == 0) {
                // fold (W_in_2 @ I)[m] into this chunk's partial
                const float* w2 = Win2 + (size_t)m * KK;
                acc += w2[tid] * I[tid] + w2[tid + 256] * I[tid + 256];
            }
            acc = warp_sum(acc);
            if (lane == 0) s_red[warp] = acc;
            __syncthreads();
            if (tid == 0) {
                float t = 0.0f;
#pragma unroll
                for (int w = 0; w < 8; w++) t += s_red[w];
                g_part[m * SPLIT + c] = t;
                __threadfence();                       // publish partial
                int old = atomicAdd(&g_cnt[m], 1);
                if (old == SPLIT - 1) {
                    // last chunk of row m: combine (deterministic fixed order)
                    g_cnt[m] = 0;                      // reset for next replay
                    __threadfence();                   // acquire partials
                    float s = 0.0f;
#pragma unroll
                    for (int c2 = 0; c2 < SPLIT; c2++) s += g_part[m * SPLIT + c2];
                    float zm  = z[m];
                    float psi = tanhf(zm);
                    out_z[m] = (1.0f - GAMMA * TAU) * zm +
                               (GAMMA * TAU) * (F[m] * psi + s);
                }
            }
        }
    } else {
        // ===== Hebbian fixup for kPre rows [0,16384): out_W += g*C*phi*phi ====
        s_phi[tid] = g_phi[tid];
        __syncthreads();
        int idx = (bid - STRIPE_BLKS) * 256 + tid;   // float4 idx, 0..4095
        int p = idx * 4;                              // < 16384
        int i = p >> 8;
        int j = p & 255;
        float pi = s_phi[i];
        float4 cc = ((const float4*)C)[idx];
        float4 w  = ((float4*)out_W)[idx];
        w.x += GAMMA * cc.x * pi * s_phi[j];
        w.y += GAMMA * cc.y * pi * s_phi[j + 1];
        w.z += GAMMA * cc.z * pi * s_phi[j + 2];
        w.w += GAMMA * cc.w * pi * s_phi[j + 3];
        ((float4*)out_W)[idx] = w;
    }
}

// ---------------------------------------------------------------------------
// Launch: inputs in metadata order: I, x, W, z, C, D, F, H, W_in_1, W_in_2.
// Output: concat(x_new[256], W_new[65536], z_new[512]) = 66304 floats.
// ---------------------------------------------------------------------------
extern "C" void kernel_launch(void* const* d_in, const int* in_sizes, int n_in,
                              void* d_out, int out_size) {
    const float* I    = (const float*)d_in[0];
    const float* x    = (const float*)d_in[1];
    const float* W    = (const float*)d_in[2];
    const float* z    = (const float*)d_in[3];
    const float* C    = (const float*)d_in[4];
    const float* D    = (const float*)d_in[5];
    const float* F    = (const float*)d_in[6];
    const float* H    = (const float*)d_in[7];
    const float* Win1 = (const float*)d_in[8];
    const float* Win2 = (const float*)d_in[9];

    float* out_x = (float*)d_out;            // [0, 256)
    float* out_W = out_x + NN;               // [256, 256+65536)
    float* out_z = out_W + NN2;              // [65792, 66304)

    // Kernel 1: x_new/phi setup hidden under a phi-free D-partial stream
    kPre<<<KPRE_BLKS, 256>>>(x, W, Win1, I, D, z, out_x, out_W);

    // Kernel 2: remaining D (with Hebbian) striped with H, + fixup tail
    kMain<<<KMAIN_BLKS, 256>>>(W, C, D, z, H, F, Win2, I, out_W, out_z);
}

// round 12
// speedup vs baseline: 1.1619x; 1.0040x over previous
#include <cuda_runtime.h>

// Problem constants
#define GAMMA 0.1f
#define TAU   0.01f
#define NN    256          // neuron count
#define MM    512          // astrocyte count
#define KK    512          // input dim
#define NN2   (NN * NN)    // 65536
#define SPLIT 8            // chunks per H row (32 KB each)
#define CHUNK (NN2 / SPLIT) // 8192 floats per chunk

#define SETUP_BLKS 32
#define D_ROWS_PER_BLK 16

// Kernel 1: setup + first slice of D (phi-free partial)
#define PRE_D_BLKS  1024
#define PRE_D_ROWS  (PRE_D_BLKS * D_ROWS_PER_BLK)   // 16384
#define KPRE_BLKS   (SETUP_BLKS + PRE_D_BLKS)       // 1056

// Kernel 2: fixup first, then H contiguous, then remaining D contiguous
#define FIX_BLKS    (PRE_D_ROWS / (256 * 4))         // 16
#define H_BLKS      (MM * SPLIT)                     // 4096
#define MAIN_D_BLKS ((NN2 - PRE_D_ROWS) / D_ROWS_PER_BLK)  // 3072
#define H_START     FIX_BLKS                         // 16
#define D_START     (FIX_BLKS + H_BLKS)              // 4112
#define KMAIN_BLKS  (FIX_BLKS + H_BLKS + MAIN_D_BLKS) // 7184

// Scratch (no allocations allowed in kernel_launch)
__device__ float g_phi[NN];           // sigmoid(x_new)
__device__ float g_part[MM * SPLIT];  // H@Phi partial sums (chunk 0 folds win2)
__device__ int   g_cnt[MM];           // per-row H-chunk arrival counters (self-reset)

__device__ __forceinline__ float warp_sum(float v) {
#pragma unroll
    for (int o = 16; o > 0; o >>= 1) v += __shfl_xor_sync(0xffffffffu, v, o);
    return v;
}

__device__ __forceinline__ float sigmoidf(float v) {
    return 1.0f / (1.0f + expf(-v));
}

// ---------------------------------------------------------------------------
// Kernel 1 (kPre): 1056 blocks x 256 threads. NO internal dependencies.
//   blocks [0, 32)     : x_new + g_phi (warp-per-row; hides under D stream)
//   blocks [32, 1056)  : W_new PARTIAL = (1-g)W + g*(D@psi) for rows [0,16384)
// ---------------------------------------------------------------------------
__global__ void __launch_bounds__(256) kPre(
    const float* __restrict__ x,    const float* __restrict__ W,
    const float* __restrict__ Win1, const float* __restrict__ I,
    const float* __restrict__ D,    const float* __restrict__ z,
    float* __restrict__ out_x, float* __restrict__ out_W) {

    __shared__ float s_vec[MM];
    int tid  = threadIdx.x;  // 256
    int warp = tid >> 5, lane = tid & 31;
    unsigned bid = blockIdx.x;

    if (bid < SETUP_BLKS) {
        // ================= setup: x_new + phi (8 rows/block) =================
        __shared__ float s_Ilo[256];
        s_vec[tid]       = sigmoidf(x[tid]);     // s_vec[0..255] = sigmoid(x)
        s_vec[tid + 256] = I[tid + 256];         // s_vec[256..511] = I hi half
        s_Ilo[tid] = I[tid];
        __syncthreads();

        int row = bid * 8 + warp;
        float a1 = 0.0f, a2 = 0.0f;
        const float* wr = W + (size_t)row * NN;
#pragma unroll
        for (int j = lane; j < NN; j += 32) a1 += wr[j] * s_vec[j];
        const float* w1 = Win1 + (size_t)row * KK;
#pragma unroll
        for (int k = lane; k < 256; k += 32) {
            a2 += w1[k] * s_Ilo[k] + w1[k + 256] * s_vec[k + 256];
        }
        a1 = warp_sum(a1);
        a2 = warp_sum(a2);
        if (lane == 0) {
            float xn = (1.0f - GAMMA) * x[row] + GAMMA * a1 + a2;
            out_x[row] = xn;
            g_phi[row] = sigmoidf(xn);
        }
    } else {
        // ========== W_new partial: 2 rows/warp D GEMV (no phi) ==========
        s_vec[tid]       = tanhf(z[tid]);
        s_vec[tid + 256] = tanhf(z[tid + 256]);
        __syncthreads();

        int p0 = (bid - SETUP_BLKS) * D_ROWS_PER_BLK + warp * 2;  // rows p0, p0+1
        const float4* dr0 = (const float4*)(D + (size_t)p0 * MM);
        const float4* dr1 = (const float4*)(D + (size_t)(p0 + 1) * MM);
        const float4* ps  = (const float4*)s_vec;

        float4 a0[4], a1[4];
#pragma unroll
        for (int q = 0; q < 4; q++) a0[q] = dr0[lane + 32 * q];  // 8 loads
#pragma unroll
        for (int q = 0; q < 4; q++) a1[q] = dr1[lane + 32 * q];  // in flight

        float acc0 = 0.0f, acc1 = 0.0f;
#pragma unroll
        for (int q = 0; q < 4; q++) {
            float4 s = ps[lane + 32 * q];
            acc0 += a0[q].x * s.x + a0[q].y * s.y + a0[q].z * s.z + a0[q].w * s.w;
            acc1 += a1[q].x * s.x + a1[q].y * s.y + a1[q].z * s.z + a1[q].w * s.w;
        }
        acc0 = warp_sum(acc0);
        acc1 = warp_sum(acc1);
        if (lane == 0) {
            out_W[p0]     = (1.0f - GAMMA) * W[p0]     + GAMMA * acc0;
            out_W[p0 + 1] = (1.0f - GAMMA) * W[p0 + 1] + GAMMA * acc1;
        }
    }
}

// ---------------------------------------------------------------------------
// Kernel 2 (kMain): 7184 blocks x 256 threads. phi ready via kernel boundary.
//   blocks [0, 16)       : Hebbian fixup for kPre rows [0, 16384) — runs first,
//                          no tail straggler.
//   blocks [16, 4112)    : H@Phi 32KB-chunk partials (chunk 0 folds Win2@I);
//                          last chunk per row combines z_new.
//   blocks [4112, 7184)  : D rows [16384, 65536) with Hebbian applied directly.
// Contiguous H-then-D ordering (R8's proven best streaming arrangement).
// ---------------------------------------------------------------------------
__global__ void __launch_bounds__(256) kMain(
    const float* __restrict__ W, const float* __restrict__ C,
    const float* __restrict__ D, const float* __restrict__ z,
    const float* __restrict__ H, const float* __restrict__ F,
    const float* __restrict__ Win2, const float* __restrict__ I,
    float* __restrict__ out_W, float* __restrict__ out_z) {

    __shared__ float s_vec[MM];   // psi(z) for D branch; phi for H/fixup branch
    __shared__ float s_phi[NN];   // phi (D branch Hebbian)
    __shared__ float s_red[8];
    int tid  = threadIdx.x;  // 256
    int warp = tid >> 5, lane = tid & 31;
    unsigned bid = blockIdx.x;

    if (bid < FIX_BLKS) {
        // ===== Hebbian fixup for kPre rows [0,16384): out_W += g*C*phi*phi ====
        s_vec[tid] = g_phi[tid];
        __syncthreads();
        int idx = bid * 256 + tid;   // float4 idx, 0..4095
        int p = idx * 4;             // < 16384
        int i = p >> 8;
        int j = p & 255;
        float pi = s_vec[i];
        float4 cc = ((const float4*)C)[idx];
        float4 w  = ((float4*)out_W)[idx];
        w.x += GAMMA * cc.x * pi * s_vec[j];
        w.y += GAMMA * cc.y * pi * s_vec[j + 1];
        w.z += GAMMA * cc.z * pi * s_vec[j + 2];
        w.w += GAMMA * cc.w * pi * s_vec[j + 3];
        ((float4*)out_W)[idx] = w;
    } else if (bid < D_START) {
        // ========== H@Phi partial, 32 KB/block (+win2 on chunk 0) ==========
        int hIdx = bid - H_START;    // 0..4095
        s_vec[tid] = g_phi[tid];
        __syncthreads();

        int c = hIdx & (SPLIT - 1);  // chunk
        int m = hIdx >> 3;           // row
        const float4* hr = (const float4*)(H + (size_t)m * NN2 + (size_t)c * CHUNK);

        float4 h[8];
#pragma unroll
        for (int q = 0; q < 8; q++) h[q] = hr[tid + 256 * q];  // 8 in flight

        float acc = 0.0f;
#pragma unroll
        for (int q = 0; q < 8; q++) {
            int p = c * CHUNK + (tid + 256 * q) * 4;  // element index in row
            int i = p >> 8;
            int j = p & 255;              // multiple of 4, j+3 <= 255
            float pi = s_vec[i];
            acc += pi * (h[q].x * s_vec[j]     + h[q].y * s_vec[j + 1] +
                         h[q].z * s_vec[j + 2] + h[q].w * s_vec[j + 3]);
        }
        if (c == 0) {
            // fold (W_in_2 @ I)[m] into this chunk's partial
            const float* w2 = Win2 + (size_t)m * KK;
            acc += w2[tid] * I[tid] + w2[tid + 256] * I[tid + 256];
        }
        acc = warp_sum(acc);
        if (lane == 0) s_red[warp] = acc;
        __syncthreads();
        if (tid == 0) {
            float t = 0.0f;
#pragma unroll
            for (int w = 0; w < 8; w++) t += s_red[w];
            g_part[m * SPLIT + c] = t;
            __threadfence();                       // publish partial
            int old = atomicAdd(&g_cnt[m], 1);
            if (old == SPLIT - 1) {
                // last chunk of row m: combine (deterministic fixed order)
                g_cnt[m] = 0;                      // reset for next replay
                __threadfence();                   // acquire partials
                float s = 0.0f;
#pragma unroll
                for (int c2 = 0; c2 < SPLIT; c2++) s += g_part[m * SPLIT + c2];
                float zm  = z[m];
                float psi = tanhf(zm);
                out_z[m] = (1.0f - GAMMA * TAU) * zm +
                           (GAMMA * TAU) * (F[m] * psi + s);
            }
        }
    } else {
        // ========== D: 2 rows/warp GEMV + Hebbian (phi ready) ==========
        int dIdx = bid - D_START;    // 0..3071
        s_vec[tid]       = tanhf(z[tid]);
        s_vec[tid + 256] = tanhf(z[tid + 256]);
        s_phi[tid]       = g_phi[tid];
        __syncthreads();

        int p0 = PRE_D_ROWS + dIdx * D_ROWS_PER_BLK + warp * 2;
        const float4* dr0 = (const float4*)(D + (size_t)p0 * MM);
        const float4* dr1 = (const float4*)(D + (size_t)(p0 + 1) * MM);
        const float4* ps  = (const float4*)s_vec;

        float4 a0[4], a1[4];
#pragma unroll
        for (int q = 0; q < 4; q++) a0[q] = dr0[lane + 32 * q];
#pragma unroll
        for (int q = 0; q < 4; q++) a1[q] = dr1[lane + 32 * q];

        float acc0 = 0.0f, acc1 = 0.0f;
#pragma unroll
        for (int q = 0; q < 4; q++) {
            float4 s = ps[lane + 32 * q];
            acc0 += a0[q].x * s.x + a0[q].y * s.y + a0[q].z * s.z + a0[q].w * s.w;
            acc1 += a1[q].x * s.x + a1[q].y * s.y + a1[q].z * s.z + a1[q].w * s.w;
        }
        acc0 = warp_sum(acc0);
        acc1 = warp_sum(acc1);
        if (lane == 0) {
            int i = p0 >> 8;                 // p0 even => same i both rows
            int j0 = p0 & 255;
            float pi = s_phi[i];
            float ph0 = pi * s_phi[j0];
            float ph1 = pi * s_phi[j0 + 1];
            out_W[p0]     = (1.0f - GAMMA) * W[p0]
                          + GAMMA * (C[p0] * ph0 + acc0);
            out_W[p0 + 1] = (1.0f - GAMMA) * W[p0 + 1]
                          + GAMMA * (C[p0 + 1] * ph1 + acc1);
        }
    }
}

// ---------------------------------------------------------------------------
// Launch: inputs in metadata order: I, x, W, z, C, D, F, H, W_in_1, W_in_2.
// Output: concat(x_new[256], W_new[65536], z_new[512]) = 66304 floats.
// ---------------------------------------------------------------------------
extern "C" void kernel_launch(void* const* d_in, const int* in_sizes, int n_in,
                              void* d_out, int out_size) {
    const float* I    = (const float*)d_in[0];
    const float* x    = (const float*)d_in[1];
    const float* W    = (const float*)d_in[2];
    const float* z    = (const float*)d_in[3];
    const float* C    = (const float*)d_in[4];
    const float* D    = (const float*)d_in[5];
    const float* F    = (const float*)d_in[6];
    const float* H    = (const float*)d_in[7];
    const float* Win1 = (const float*)d_in[8];
    const float* Win2 = (const float*)d_in[9];

    float* out_x = (float*)d_out;            // [0, 256)
    float* out_W = out_x + NN;               // [256, 256+65536)
    float* out_z = out_W + NN2;              // [65792, 66304)

    // Kernel 1: x_new/phi setup hidden under a phi-free D-partial stream
    kPre<<<KPRE_BLKS, 256>>>(x, W, Win1, I, D, z, out_x, out_W);

    // Kernel 2: fixup (first) + H stream + remaining D stream
    kMain<<<KMAIN_BLKS, 256>>>(W, C, D, z, H, F, Win2, I, out_W, out_z);
}